// round 8
// baseline (speedup 1.0000x reference)
#include <cuda_runtime.h>
#include <mma.h>
#include <cstdint>
#include <math.h>

using namespace nvcuda;

#define Bsz   64
#define Hh    2048
#define G4    8192
#define INs   1024
#define Tt    128
#define STAGES 4
#define BK    64
#define LDA   68               // 64 floats + 4 pad
#define LDG   36               // epilogue: 32 cols + 4 pad
#define NLSTM 256
#define NREC  32
#define NT    192              // 4 consumer warps + 2 producer warps

#define A_STAGE_FLOATS (64*LDA)            // 4352
#define B_STAGE_FLOATS (32*LDA)            // 2176
#define STAGE_FLOATS   (A_STAGE_FLOATS + B_STAGE_FLOATS)   // 6528 -> 26112 B
#define BSUM_OFF       (STAGES*STAGE_FLOATS)               // float offset
#define MBAR_OFF       (BSUM_OFF + 32)                     // float offset (8B aligned)
#define SMEM_BYTES     ((MBAR_OFF + 16)*4)                 // 104640 B

// ---- persistent device scratch ----
__device__ float g_Wih[2L*G4*Hh];
__device__ float g_Whh[2L*G4*Hh];
__device__ float g_Wrec[(long)INs*Hh];
__device__ float g_h[4L*Bsz*Hh];
__device__ float g_c[2L*Bsz*Hh];
__device__ float g_x0[(long)Bsz*Hh];

__device__ __forceinline__ float tf32r(float x){
  uint32_t r; asm("cvt.rna.tf32.f32 %0, %1;" : "=r"(r) : "f"(x));
  return __uint_as_float(r);
}
__device__ __forceinline__ uint32_t saddr(const void* p){
  return (uint32_t)__cvta_generic_to_shared(p);
}
__device__ __forceinline__ void cpa16(uint32_t d, const void* s){
  asm volatile("cp.async.cg.shared.global [%0], [%1], 16;" :: "r"(d), "l"(s));
}
__device__ __forceinline__ float sigf(float x){ return 1.f/(1.f+expf(-x)); }
__device__ __forceinline__ void mwait(uint32_t mbar, uint32_t parity){
  asm volatile("{\n\t.reg .pred P;\n"
    "W%=:\n\tmbarrier.try_wait.parity.acquire.cta.shared::cta.b64 P, [%0], %1;\n"
    "\t@!P bra W%=;\n\t}" :: "r"(mbar), "r"(parity) : "memory");
}
__device__ __forceinline__ void marrive(uint32_t mbar){
  asm volatile("{\n\t.reg .b64 t;\n\tmbarrier.arrive.release.cta.shared::cta.b64 t, [%0];\n\t}"
    :: "r"(mbar) : "memory");
}
__device__ __forceinline__ void cpa_arrive(uint32_t mbar){
  asm volatile("cp.async.mbarrier.arrive.noinc.shared::cta.b64 [%0];" :: "r"(mbar) : "memory");
}

// ---- init: round weights/state to tf32 (rna) ----
__global__ void init_kernel(const float* __restrict__ h0, const float* __restrict__ c0,
                            const float* __restrict__ Wih, const float* __restrict__ Whh,
                            const float* __restrict__ Wrec)
{
  long tid = (long)blockIdx.x*blockDim.x + threadIdx.x;
  long stride = (long)gridDim.x*blockDim.x;

  const long NW = (2L*G4*Hh)/4;
  const float4* s1 = (const float4*)Wih; float4* d1 = (float4*)g_Wih;
  const float4* s2 = (const float4*)Whh; float4* d2 = (float4*)g_Whh;
  for (long i=tid;i<NW;i+=stride){
    float4 v=s1[i]; v.x=tf32r(v.x); v.y=tf32r(v.y); v.z=tf32r(v.z); v.w=tf32r(v.w); d1[i]=v;
    float4 u=s2[i]; u.x=tf32r(u.x); u.y=tf32r(u.y); u.z=tf32r(u.z); u.w=tf32r(u.w); d2[i]=u;
  }
  const long NR = ((long)INs*Hh)/4;
  const float4* s3 = (const float4*)Wrec; float4* d3 = (float4*)g_Wrec;
  for (long i=tid;i<NR;i+=stride){
    float4 v=s3[i]; v.x=tf32r(v.x); v.y=tf32r(v.y); v.z=tf32r(v.z); v.w=tf32r(v.w); d3[i]=v;
  }
  const long NS = ((long)Bsz*Hh)/4;
  const float4* hs = (const float4*)h0; const float4* cs = (const float4*)c0;
  float4* gh = (float4*)g_h; float4* gc = (float4*)g_c; float4* gx = (float4*)g_x0;
  for (long i=tid;i<NS;i+=stride){
    float4 v0=hs[i];    v0.x=tf32r(v0.x); v0.y=tf32r(v0.y); v0.z=tf32r(v0.z); v0.w=tf32r(v0.w);
    float4 v1=hs[NS+i]; v1.x=tf32r(v1.x); v1.y=tf32r(v1.y); v1.z=tf32r(v1.z); v1.w=tf32r(v1.w);
    gh[1*NS + i] = v0;
    gh[3*NS + i] = v1;
    gc[i]      = cs[i];
    gc[NS + i] = cs[NS + i];
    gx[i] = make_float4(0.f,0.f,0.f,0.f);
  }
}

// ---- fused layer-step kernel: warp-specialized wmma tf32 GEMM + LSTM cell ----
// Consumers: warps 0-3 (tid 0..127). Producers: warps 4-5 (tid 128..191).
__global__ void __launch_bounds__(NT,2) lstm_kernel(
  const float* __restrict__ Ax, const float* __restrict__ Ah,
  const float* __restrict__ Wih, const float* __restrict__ Whh,
  const float* __restrict__ bih, const float* __restrict__ bhh,
  float* __restrict__ c_io, float* __restrict__ h_out,
  int n_lstm,
  const float* __restrict__ Arec, const float* __restrict__ Wrec,
  const float* __restrict__ brec, float* __restrict__ out_rec)
{
  extern __shared__ float smem[];
  const int tid = threadIdx.x;
  const bool is_rec = (int)blockIdx.x >= n_lstm;
  const int KT  = is_rec ? (Hh/BK) : (2*Hh/BK);        // 32 or 64
  const int j0  = is_rec ? 0 : (int)blockIdx.x*8;
  const int rn0 = is_rec ? ((int)blockIdx.x - n_lstm)*32 : 0;
  const float* A0 = is_rec ? Arec : Ax;

  const uint32_t sbase = saddr(smem);
  const uint32_t mb_full = sbase + MBAR_OFF*4;         // full[0..3], 8B each
  const uint32_t mb_free = mb_full + 32;               // free[0..3]

  if (tid == 0){
    #pragma unroll
    for (int s=0;s<STAGES;s++){
      asm volatile("mbarrier.init.shared.b64 [%0], 64;"  :: "r"(mb_full + s*8) : "memory");
      asm volatile("mbarrier.init.shared.b64 [%0], 128;" :: "r"(mb_free + s*8) : "memory");
    }
  }
  // bias sums
  if (tid < 32){
    float bs;
    if (is_rec) bs = brec[rn0 + tid];
    else { int g = tid>>3, j = j0 + (tid&7); bs = bih[g*Hh + j] + bhh[g*Hh + j]; }
    smem[BSUM_OFF + tid] = bs;
  }
  __syncthreads();   // mbarriers + bias visible before pipeline starts

  if (tid >= 128){
    // ---------------- producers (64 threads) ----------------
    const int p = tid - 128;
    // A: row p, 16x16B chunks (64 floats). B: row p>>1, half (p&1): 8x16B.
    const int br = p >> 1, bh = (p & 1)*32;
    const float* bw_lo; const float* bw_hi;
    if (is_rec){ bw_lo = Wrec + (long)(rn0+br)*Hh; bw_hi = bw_lo; }
    else { long wr = (long)(br>>3)*Hh + j0 + (br&7); bw_lo = Wih + wr*Hh; bw_hi = Whh + wr*Hh; }
    const float* arow_lo = A0 + (long)p*Hh;
    const float* arow_hi = Ah + (long)p*Hh;

    for (int kt=0; kt<KT; ++kt){
      const int s = kt & 3, u = kt >> 2;
      if (u > 0) mwait(mb_free + s*8, (uint32_t)((u-1)&1));
      const int kb = kt*BK;
      const bool lo = (is_rec || kb < Hh);
      float* stg = smem + s*STAGE_FLOATS;
      {
        const float* src = lo ? (arow_lo + kb) : (arow_hi + kb - Hh);
        const uint32_t d0 = saddr(&stg[p*LDA]);
        #pragma unroll
        for (int i=0;i<16;i++) cpa16(d0 + i*16, src + i*4);
      }
      {
        const float* src = (lo ? (bw_lo + kb) : (bw_hi + kb - Hh)) + bh;
        const uint32_t d0 = saddr(&stg[A_STAGE_FLOATS + br*LDA + bh]);
        #pragma unroll
        for (int i=0;i<8;i++) cpa16(d0 + i*16, src + i*4);
      }
      cpa_arrive(mb_full + s*8);
    }
  } else {
    // ---------------- consumers (4 warps, 128 threads) ----------------
    using FA = wmma::fragment<wmma::matrix_a,16,16,8,wmma::precision::tf32,wmma::row_major>;
    using FB = wmma::fragment<wmma::matrix_b,16,16,8,wmma::precision::tf32,wmma::col_major>;
    using FC = wmma::fragment<wmma::accumulator,16,16,8,float>;
    const int w   = tid>>5;
    const int wm0 = (w>>1)*32;       // 0 or 32 (plus +16 sub-tile)
    const int wn  = (w&1)*16;        // 0 or 16

    FC acc[2];
    wmma::fill_fragment(acc[0], 0.0f);
    wmma::fill_fragment(acc[1], 0.0f);

    for (int kt=0; kt<KT; ++kt){
      const int s = kt & 3;
      mwait(mb_full + s*8, (uint32_t)((kt>>2)&1));
      const float* stg  = smem + s*STAGE_FLOATS;
      const float* stgB = stg + A_STAGE_FLOATS;
      #pragma unroll
      for (int kk=0; kk<BK/8; ++kk){
        FA a0, a1; FB b;
        wmma::load_matrix_sync(a0, &stg[(wm0   )*LDA + kk*8], LDA);
        wmma::load_matrix_sync(a1, &stg[(wm0+16)*LDA + kk*8], LDA);
        wmma::load_matrix_sync(b,  &stgB[wn*LDA + kk*8], LDA);
        wmma::mma_sync(acc[0], a0, b, acc[0]);
        wmma::mma_sync(acc[1], a1, b, acc[1]);
      }
      marrive(mb_free + s*8);
    }
    // park accumulators in smem after the barrier below
    __syncthreads();   // (1) all loads done; safe to reuse stage smem
    wmma::store_matrix_sync(&smem[(wm0   )*LDG + wn], acc[0], LDG, wmma::mem_row_major);
    wmma::store_matrix_sync(&smem[(wm0+16)*LDG + wn], acc[1], LDG, wmma::mem_row_major);
    goto epilogue_sync;
  }
  __syncthreads();     // (1) producers join here
  epilogue_sync:
  __syncthreads();     // (2) accumulators staged

  {
    const float* ep = smem;
    const float* bs = smem + BSUM_OFF;
    if (!is_rec){
      for (int idx=tid; idx<Bsz*8; idx+=NT){
        int b = idx>>3, jj = idx&7, j = j0+jj;
        float iv = ep[b*LDG + jj]      + bs[jj];
        float fv = ep[b*LDG + 8+jj]    + bs[8+jj];
        float gv = ep[b*LDG + 16+jj]   + bs[16+jj];
        float ov = ep[b*LDG + 24+jj]   + bs[24+jj];
        float co = c_io[(long)b*Hh + j];
        float cn = sigf(fv)*co + sigf(iv)*tanhf(gv);
        float hn = sigf(ov)*tanhf(cn);
        c_io[(long)b*Hh + j]  = cn;
        h_out[(long)b*Hh + j] = tf32r(hn);
      }
    } else {
      for (int idx=tid; idx<Bsz*32; idx+=NT){
        int b = idx>>5, nn = idx&31;
        out_rec[(long)b*INs + rn0 + nn] = ep[b*LDG+nn] + bs[nn];
      }
    }
  }
}

extern "C" void kernel_launch(void* const* d_in, const int* in_sizes, int n_in,
                              void* d_out, int out_size)
{
  const float* h0  = (const float*)d_in[1];
  const float* c0  = (const float*)d_in[2];
  const float* Wih = (const float*)d_in[3];
  const float* Whh = (const float*)d_in[4];
  const float* bih = (const float*)d_in[5];
  const float* bhh = (const float*)d_in[6];
  const float* Wrec= (const float*)d_in[7];
  const float* brec= (const float*)d_in[8];
  float* out = (float*)d_out;

  void *p0,*p1,*p2,*p3,*p4,*p5;
  cudaGetSymbolAddress(&p0, g_Wih);
  cudaGetSymbolAddress(&p1, g_Whh);
  cudaGetSymbolAddress(&p2, g_Wrec);
  cudaGetSymbolAddress(&p3, g_h);
  cudaGetSymbolAddress(&p4, g_c);
  cudaGetSymbolAddress(&p5, g_x0);
  float* gWih = (float*)p0; float* gWhh = (float*)p1; float* gWrec = (float*)p2;
  float* gH   = (float*)p3; float* gC   = (float*)p4; float* gX0  = (float*)p5;

  cudaFuncSetAttribute(lstm_kernel, cudaFuncAttributeMaxDynamicSharedMemorySize, SMEM_BYTES);

  init_kernel<<<1024,256>>>(h0, c0, Wih, Whh, Wrec);

  const long NS = (long)Bsz*Hh;
  const long WOFF = (long)G4*Hh;

  for (int t=0; t<Tt; ++t){
    int rp = (t+1)&1, wp = t&1;
    float* h0r = gH + (0*2+rp)*NS;
    float* h0w = gH + (0*2+wp)*NS;
    float* h1r = gH + (1*2+rp)*NS;
    float* h1w = gH + (1*2+wp)*NS;
    const float* x = (t==0) ? gX0 : h1r;
    float* orow = (t==0) ? out : (out + (long)(Tt-t)*Bsz*INs);

    // layer 0 (+ fused recons of previous step's h1 when t>0)
    lstm_kernel<<<(t==0?NLSTM:NLSTM+NREC),NT,SMEM_BYTES>>>(
      x, h0r, gWih, gWhh, bih, bhh, gC, h0w,
      NLSTM, x, gWrec, brec, orow);

    // layer 1
    lstm_kernel<<<NLSTM,NT,SMEM_BYTES>>>(
      h0w, h1r, gWih + WOFF, gWhh + WOFF,
      bih + G4, bhh + G4, gC + NS, h1w,
      NLSTM, nullptr, gWrec, brec, nullptr);
  }

  // final recons of h1(127) -> output row 0
  lstm_kernel<<<NREC,NT,SMEM_BYTES>>>(
    gX0, gX0, gWih, gWhh, bih, bhh, gC, gX0,
    0, gH + (1*2+1)*NS, gWrec, brec, out);
}